// round 4
// baseline (speedup 1.0000x reference)
#include <cuda_runtime.h>
#include <cstdint>
#include <math.h>

namespace {

typedef unsigned long long ull;

constexpr int  B_  = 128;
constexpr int  T_  = 256;
constexpr int  R_  = 130;
constexpr int  H_  = 1024;
constexpr int  H3_ = 3072;
constexpr int  Z2_ = 256;
constexpr int  C_  = 24;
constexpr int  ZC_ = 280;                 // Z2 + C
constexpr long BT_ = (long)B_ * T_;       // 32768
constexpr long BH_ = (long)B_ * H_;

constexpr int NB = 128;   // persistent grid size (must all be co-resident)
constexpr int KC = 32;    // k-chunk
constexpr int MT = 64;    // m tile
constexpr int NJ = 16;    // j (h-column) tile

// ------------------------- device scratch ----------------------------------
__device__ float g_hf[2][B_ * H_];
__device__ float g_hb[2][B_ * H_];
__device__ float g_h0[2][B_ * H_];
__device__ float g_h1[2][B_ * H_];
__device__ float g_gif[BT_ * H3_];        // encoder fwd input gates, row m=b*T+t
__device__ float g_gib[BT_ * H3_];        // encoder bwd input gates
__device__ float g_gid[BT_ * H3_];        // decoder dec_in input gates
__device__ float g_zi [B_ * H3_];         // z-part of decoder L1 gates (+b_ih_g)
__device__ float g_h1all[BT_ * H_];       // all decoder layer-2 hiddens
__device__ float g_henc[B_ * 2 * H_];
__device__ float g_var [B_ * Z2_];
__device__ float g_zbuf[B_ * ZC_];
__device__ float g_decin[BT_ * R_];
__device__ float g_logits[BT_ * R_];
__device__ unsigned g_bar_count;
__device__ volatile unsigned g_bar_gen;

// --------------------------- f32x2 helpers ---------------------------------
__device__ __forceinline__ ull pack2(float x, float y) {
    ull r; asm("mov.b64 %0, {%1, %2};" : "=l"(r) : "f"(x), "f"(y)); return r;
}
__device__ __forceinline__ float2 unpack2(ull v) {
    float2 f; asm("mov.b64 {%0, %1}, %2;" : "=f"(f.x), "=f"(f.y) : "l"(v)); return f;
}
__device__ __forceinline__ void fma2(ull& d, ull a, ull b) {
    asm("fma.rn.f32x2 %0, %1, %2, %0;" : "+l"(d) : "l"(a), "l"(b));
}
__device__ __forceinline__ float sigmoidf_(float x) { return 1.f / (1.f + expf(-x)); }

// ------------------------ software grid barrier ----------------------------
__device__ __forceinline__ void grid_barrier() {
    __syncthreads();
    if (threadIdx.x == 0) {
        unsigned gen = g_bar_gen;
        __threadfence();
        if (atomicAdd(&g_bar_count, 1u) == (unsigned)(NB - 1)) {
            g_bar_count = 0;
            __threadfence();
            g_bar_gen = gen + 1;
        } else {
            while (g_bar_gen == gen) { }
        }
        __threadfence();
    }
    __syncthreads();
}

// ------------------------------- GEMM --------------------------------------
// C[M,N] = A[M,K] (row-major) @ W[N,K]^T (row-major) + bias  (f32x2 packed)
struct GArgs {
    const float* A;  long lda;
    const float* W;  long ldw;
    const float* bias;
    float*       C;  long ldc;
    int M, N, K;
};

constexpr int GBM = 64, GBN = 64, GBK = 16;

__global__ void gemm_nt_kernel(GArgs g0, GArgs g1) {
    GArgs g = (blockIdx.z == 0) ? g0 : g1;
    const int bm = blockIdx.y * GBM;
    const int bn = blockIdx.x * GBN;
    if (bm >= g.M || bn >= g.N) return;

    __shared__ float As[GBK][GBM + 2];
    __shared__ float Bs[GBK][GBN + 2];

    const int tid = threadIdx.x;      // 256 threads
    const int tx  = tid & 15;
    const int ty  = tid >> 4;

    ull acc[4][2];
#pragma unroll
    for (int i = 0; i < 4; i++) { acc[i][0] = 0ull; acc[i][1] = 0ull; }

    for (int k0 = 0; k0 < g.K; k0 += GBK) {
#pragma unroll
        for (int i = 0; i < 4; i++) {
            int idx = tid + i * 256;
            int m = idx >> 4, k = idx & 15;
            int gm = bm + m, gk = k0 + k;
            float v = 0.f;
            if (gm < g.M && gk < g.K) v = g.A[(long)gm * g.lda + gk];
            As[k][m] = v;
        }
#pragma unroll
        for (int i = 0; i < 4; i++) {
            int idx = tid + i * 256;
            int n = idx >> 4, k = idx & 15;
            int gn = bn + n, gk = k0 + k;
            float v = 0.f;
            if (gn < g.N && gk < g.K) v = g.W[(long)gn * g.ldw + gk];
            Bs[k][n] = v;
        }
        __syncthreads();
#pragma unroll
        for (int kk = 0; kk < GBK; kk++) {
            ull b0 = *(const ull*)&Bs[kk][tx * 4];
            ull b1 = *(const ull*)&Bs[kk][tx * 4 + 2];
#pragma unroll
            for (int i = 0; i < 4; i++) {
                float a = As[kk][ty * 4 + i];
                ull a2 = pack2(a, a);
                fma2(acc[i][0], a2, b0);
                fma2(acc[i][1], a2, b1);
            }
        }
        __syncthreads();
    }

#pragma unroll
    for (int i = 0; i < 4; i++) {
        int gm = bm + ty * 4 + i;
        if (gm >= g.M) continue;
#pragma unroll
        for (int jp = 0; jp < 2; jp++) {
            float2 v2 = unpack2(acc[i][jp]);
            int gn0 = bn + tx * 4 + jp * 2;
            if (gn0 < g.N) {
                float v = v2.x; if (g.bias) v += g.bias[gn0];
                g.C[(long)gm * g.ldc + gn0] = v;
            }
            if (gn0 + 1 < g.N) {
                float v = v2.y; if (g.bias) v += g.bias[gn0 + 1];
                g.C[(long)gm * g.ldc + gn0 + 1] = v;
            }
        }
    }
}

// -------------------- persistent encoder (bidirectional GRU) ---------------
__global__ void __launch_bounds__(256, 1)
encoder_kernel(const float* __restrict__ w_f, const float* __restrict__ bh_f,
               const float* __restrict__ w_b, const float* __restrict__ bh_b) {
    __shared__ float As[KC][MT + 2];                 // 8448 B
    __shared__ ull   Bs[3][KC][NJ + 1];              // 13056 B
    const int tid = threadIdx.x;
    const int tx  = tid & 15;       // h-column within tile
    const int ty  = tid >> 4;       // row group
    const int r0  = ty * 4;

#pragma unroll 1
    for (int t = 0; t < T_; t++) {
        const float* hfc = g_hf[t & 1];       float* hfn = g_hf[(t + 1) & 1];
        const float* hbc = g_hb[t & 1];       float* hbn = g_hb[(t + 1) & 1];
#pragma unroll 1
        for (int job = blockIdx.x; job < 256; job += NB) {
            const int jt  = job >> 2;
            const int dir = (job >> 1) & 1;
            const int mt  = job & 1;
            const float* h       = dir ? hbc : hfc;
            float*       hn_out  = dir ? hbn : hfn;
            const float* W       = dir ? w_b : w_f;
            const float* bh      = dir ? bh_b : bh_f;
            const float* gi_base = dir ? g_gib : g_gif;
            const int tstep = dir ? (T_ - 1 - t) : t;
            const int m0 = mt * MT;
            const int j0 = jt * NJ;

            ull ar[2] = {0ull, 0ull}, az[2] = {0ull, 0ull}, an[2] = {0ull, 0ull};
#pragma unroll 1
            for (int k0 = 0; k0 < H_; k0 += KC) {
                __syncthreads();
#pragma unroll
                for (int i = 0; i < 8; i++) {           // 64x32 A tile
                    int f = tid + i * 256;
                    int m = f >> 5, kk = f & 31;
                    As[kk][m] = h[(long)(m0 + m) * H_ + k0 + kk];
                }
#pragma unroll
                for (int i = 0; i < 6; i++) {           // 3x16x32 gate weights
                    int f = tid + i * 256;
                    int gg = f >> 9;
                    int r  = f & 511;
                    int n = r >> 5, kk = r & 31;
                    float w = W[(long)(gg * H_ + j0 + n) * H_ + k0 + kk];
                    Bs[gg][kk][n] = pack2(w, w);
                }
                __syncthreads();
#pragma unroll
                for (int kk = 0; kk < KC; kk++) {
                    ull a0 = *(const ull*)&As[kk][r0];
                    ull a1 = *(const ull*)&As[kk][r0 + 2];
                    ull br = Bs[0][kk][tx];
                    ull bz = Bs[1][kk][tx];
                    ull bn = Bs[2][kk][tx];
                    fma2(ar[0], a0, br); fma2(ar[1], a1, br);
                    fma2(az[0], a0, bz); fma2(az[1], a1, bz);
                    fma2(an[0], a0, bn); fma2(an[1], a1, bn);
                }
            }
            // fused GRU epilogue
            const int j = j0 + tx;
            const float bhr = bh[j], bhz = bh[H_ + j], bhn = bh[2 * H_ + j];
#pragma unroll
            for (int p = 0; p < 2; p++) {
                float2 hr2 = unpack2(ar[p]);
                float2 hz2 = unpack2(az[p]);
                float2 hn2 = unpack2(an[p]);
#pragma unroll
                for (int q = 0; q < 2; q++) {
                    int m = m0 + r0 + p * 2 + q;
                    float hr = (q ? hr2.y : hr2.x) + bhr;
                    float hz = (q ? hz2.y : hz2.x) + bhz;
                    float hn = (q ? hn2.y : hn2.x) + bhn;
                    long gio = ((long)m * T_ + tstep) * H3_ + j;
                    float ir  = gi_base[gio];
                    float iz  = gi_base[gio + H_];
                    float inn = gi_base[gio + 2 * H_];
                    float rr = sigmoidf_(ir + hr);
                    float u  = sigmoidf_(iz + hz);
                    float nn = tanhf(inn + rr * hn);
                    float hp = h[(long)m * H_ + j];
                    hn_out[(long)m * H_ + j] = (1.f - u) * nn + u * hp;
                }
            }
        }
        grid_barrier();
    }
}

// -------------------- persistent decoder (2-layer GRU) ---------------------
__global__ void __launch_bounds__(256, 1)
decoder_kernel(const float* __restrict__ w_hh_g,  const float* __restrict__ b_hh_g,
               const float* __restrict__ w_ih_g2, const float* __restrict__ w_hh_g2,
               const float* __restrict__ b_ih_g2, const float* __restrict__ b_hh_g2) {
    __shared__ __align__(16) char smem[43008];
    float* AsF  = (float*)smem;                 // [KC][66]   (A tile 1)
    float* As2F = (float*)(smem + 8448);        // [KC][66]   (A tile 2, phase B)
    ull*   BsA  = (ull*)(smem + 8448);          // phase A: 3*KC*17
    ull*   BsB  = (ull*)(smem + 16896);         // phase B: 6*KC*17

    const int tid = threadIdx.x;
    const int tx  = tid & 15;
    const int ty  = tid >> 4;
    const int r0  = ty * 4;
    const int job = blockIdx.x;                  // 128 jobs, 1 per block
    const int mt  = job & 1, jt = job >> 1;
    const int m0  = mt * MT, j0 = jt * NJ;
    const int j   = j0 + tx;

#pragma unroll 1
    for (int t = 0; t < T_; t++) {
        const float* h0c = g_h0[t & 1];
        float*       h0n = g_h0[(t + 1) & 1];
        // ---------------- phase A: layer-1 GRU ----------------
        {
            ull ar[2] = {0ull, 0ull}, az[2] = {0ull, 0ull}, an[2] = {0ull, 0ull};
#pragma unroll 1
            for (int k0 = 0; k0 < H_; k0 += KC) {
                __syncthreads();
#pragma unroll
                for (int i = 0; i < 8; i++) {
                    int f = tid + i * 256;
                    int m = f >> 5, kk = f & 31;
                    AsF[kk * 66 + m] = h0c[(long)(m0 + m) * H_ + k0 + kk];
                }
#pragma unroll
                for (int i = 0; i < 6; i++) {
                    int f = tid + i * 256;
                    int gg = f >> 9;
                    int r  = f & 511;
                    int n = r >> 5, kk = r & 31;
                    float w = w_hh_g[(long)(gg * H_ + j0 + n) * H_ + k0 + kk];
                    BsA[(gg * KC + kk) * 17 + n] = pack2(w, w);
                }
                __syncthreads();
#pragma unroll
                for (int kk = 0; kk < KC; kk++) {
                    ull a0 = *(const ull*)&AsF[kk * 66 + r0];
                    ull a1 = *(const ull*)&AsF[kk * 66 + r0 + 2];
                    ull br = BsA[(0 * KC + kk) * 17 + tx];
                    ull bz = BsA[(1 * KC + kk) * 17 + tx];
                    ull bn = BsA[(2 * KC + kk) * 17 + tx];
                    fma2(ar[0], a0, br); fma2(ar[1], a1, br);
                    fma2(az[0], a0, bz); fma2(az[1], a1, bz);
                    fma2(an[0], a0, bn); fma2(an[1], a1, bn);
                }
            }
            const float bhr = b_hh_g[j], bhz = b_hh_g[H_ + j], bhn = b_hh_g[2 * H_ + j];
#pragma unroll
            for (int p = 0; p < 2; p++) {
                float2 hr2 = unpack2(ar[p]);
                float2 hz2 = unpack2(az[p]);
                float2 hn2 = unpack2(an[p]);
#pragma unroll
                for (int q = 0; q < 2; q++) {
                    int m = m0 + r0 + p * 2 + q;
                    float hr = (q ? hr2.y : hr2.x) + bhr;
                    float hz = (q ? hz2.y : hz2.x) + bhz;
                    float hn = (q ? hn2.y : hn2.x) + bhn;
                    long zo = (long)m * H3_ + j;
                    long dof = ((long)m * T_ + t) * H3_ + j;
                    float ir  = g_gid[dof]           + g_zi[zo];
                    float iz  = g_gid[dof + H_]      + g_zi[zo + H_];
                    float inn = g_gid[dof + 2 * H_]  + g_zi[zo + 2 * H_];
                    float rr = sigmoidf_(ir + hr);
                    float u  = sigmoidf_(iz + hz);
                    float nn = tanhf(inn + rr * hn);
                    float hp = h0c[(long)m * H_ + j];
                    h0n[(long)m * H_ + j] = (1.f - u) * nn + u * hp;
                }
            }
        }
        grid_barrier();
        // ---------------- phase B: layer-2 GRU ----------------
        {
            const float* h1p = (t == 0) ? h0n : g_h1[t & 1];
            float*       h1n = g_h1[(t + 1) & 1];
            ull air[2] = {0ull, 0ull}, aiz[2] = {0ull, 0ull}, ain[2] = {0ull, 0ull};
            ull ahr[2] = {0ull, 0ull}, ahz[2] = {0ull, 0ull}, ahn[2] = {0ull, 0ull};
#pragma unroll 1
            for (int k0 = 0; k0 < H_; k0 += KC) {
                __syncthreads();
#pragma unroll
                for (int i = 0; i < 8; i++) {
                    int f = tid + i * 256;
                    int m = f >> 5, kk = f & 31;
                    AsF [kk * 66 + m] = h0n[(long)(m0 + m) * H_ + k0 + kk];
                    As2F[kk * 66 + m] = h1p[(long)(m0 + m) * H_ + k0 + kk];
                }
#pragma unroll
                for (int i = 0; i < 12; i++) {
                    int f = tid + i * 256;
                    int gg = f >> 9;
                    int r  = f & 511;
                    int n = r >> 5, kk = r & 31;
                    const float* W = (gg < 3) ? w_ih_g2 : w_hh_g2;
                    int gs = (gg < 3) ? gg : gg - 3;
                    float w = W[(long)(gs * H_ + j0 + n) * H_ + k0 + kk];
                    BsB[(gg * KC + kk) * 17 + n] = pack2(w, w);
                }
                __syncthreads();
#pragma unroll
                for (int kk = 0; kk < KC; kk++) {
                    ull a0 = *(const ull*)&AsF [kk * 66 + r0];
                    ull a1 = *(const ull*)&AsF [kk * 66 + r0 + 2];
                    ull c0 = *(const ull*)&As2F[kk * 66 + r0];
                    ull c1 = *(const ull*)&As2F[kk * 66 + r0 + 2];
                    ull bir = BsB[(0 * KC + kk) * 17 + tx];
                    ull biz = BsB[(1 * KC + kk) * 17 + tx];
                    ull bin = BsB[(2 * KC + kk) * 17 + tx];
                    ull bhr = BsB[(3 * KC + kk) * 17 + tx];
                    ull bhz = BsB[(4 * KC + kk) * 17 + tx];
                    ull bhn = BsB[(5 * KC + kk) * 17 + tx];
                    fma2(air[0], a0, bir); fma2(air[1], a1, bir);
                    fma2(aiz[0], a0, biz); fma2(aiz[1], a1, biz);
                    fma2(ain[0], a0, bin); fma2(ain[1], a1, bin);
                    fma2(ahr[0], c0, bhr); fma2(ahr[1], c1, bhr);
                    fma2(ahz[0], c0, bhz); fma2(ahz[1], c1, bhz);
                    fma2(ahn[0], c0, bhn); fma2(ahn[1], c1, bhn);
                }
            }
            const float bir = b_ih_g2[j], biz = b_ih_g2[H_ + j], bin2 = b_ih_g2[2 * H_ + j];
            const float bhr = b_hh_g2[j], bhz = b_hh_g2[H_ + j], bhn2 = b_hh_g2[2 * H_ + j];
#pragma unroll
            for (int p = 0; p < 2; p++) {
                float2 ir2 = unpack2(air[p]), iz2 = unpack2(aiz[p]), in2 = unpack2(ain[p]);
                float2 hr2 = unpack2(ahr[p]), hz2 = unpack2(ahz[p]), hn2 = unpack2(ahn[p]);
#pragma unroll
                for (int q = 0; q < 2; q++) {
                    int m = m0 + r0 + p * 2 + q;
                    float rr = sigmoidf_(((q ? ir2.y : ir2.x) + bir) + ((q ? hr2.y : hr2.x) + bhr));
                    float u  = sigmoidf_(((q ? iz2.y : iz2.x) + biz) + ((q ? hz2.y : hz2.x) + bhz));
                    float nn = tanhf(((q ? in2.y : in2.x) + bin2) + rr * ((q ? hn2.y : hn2.x) + bhn2));
                    float hp = h1p[(long)m * H_ + j];
                    float v = (1.f - u) * nn + u * hp;
                    h1n[(long)m * H_ + j] = v;
                    g_h1all[((long)m * T_ + t) * H_ + j] = v;
                }
            }
        }
        grid_barrier();
    }
}

// --------------------------- elementwise kernels ---------------------------
__global__ void init_kernel(const float* __restrict__ x) {
    long stride = (long)gridDim.x * blockDim.x;
    long i0 = (long)blockIdx.x * blockDim.x + threadIdx.x;
    if (i0 == 0) { g_bar_count = 0; g_bar_gen = 0; }
    for (long i = i0; i < BH_; i += stride) { g_hf[0][i] = 0.f; g_hb[0][i] = 0.f; }
    for (long i = i0; i < BT_ * R_; i += stride) {
        int  r = (int)(i % R_);
        long m = i / R_;
        int  t = (int)(m % T_);
        g_decin[i] = (t == 0) ? ((r == R_ - 1) ? 1.f : 0.f) : x[i - R_];
    }
}

__global__ void henc_kernel() {
    int i = blockIdx.x * blockDim.x + threadIdx.x;
    if (i >= B_ * H_) return;
    int b = i / H_, jj = i % H_;
    g_henc[(long)b * 2 * H_ + jj]      = g_hf[0][i];
    g_henc[(long)b * 2 * H_ + H_ + jj] = g_hb[0][i];
}

__global__ void zstd_kernel(const float* __restrict__ eps,
                            const float* __restrict__ chroma,
                            const float* __restrict__ mu_out,
                            float* __restrict__ std_out,
                            float* __restrict__ z_out) {
    int b = blockIdx.x;
    int jj = threadIdx.x;
    if (jj < Z2_) {
        float mu = mu_out[(long)b * Z2_ + jj];
        float sd = expf(g_var[(long)b * Z2_ + jj]);
        float z  = mu + sd * eps[(long)b * Z2_ + jj];
        std_out[(long)b * Z2_ + jj] = sd;
        z_out[(long)b * ZC_ + jj]   = z;
        g_zbuf[(long)b * ZC_ + jj]  = z;
    } else if (jj < ZC_) {
        float cv = chroma[(long)b * C_ + (jj - Z2_)];
        z_out[(long)b * ZC_ + jj]  = cv;
        g_zbuf[(long)b * ZC_ + jj] = cv;
    }
}

__global__ void logsoftmax_kernel(const float* __restrict__ logits,
                                  float* __restrict__ out) {
    long warp = ((long)blockIdx.x * blockDim.x + threadIdx.x) >> 5;
    int  lane = threadIdx.x & 31;
    if (warp >= BT_) return;
    const float* row = logits + warp * R_;
    float mx = -1e30f;
    for (int jj = lane; jj < R_; jj += 32) mx = fmaxf(mx, row[jj]);
#pragma unroll
    for (int o = 16; o; o >>= 1) mx = fmaxf(mx, __shfl_xor_sync(0xffffffff, mx, o));
    float s = 0.f;
    for (int jj = lane; jj < R_; jj += 32) s += expf(row[jj] - mx);
#pragma unroll
    for (int o = 16; o; o >>= 1) s += __shfl_xor_sync(0xffffffff, s, o);
    float lse = mx + logf(s);
    float* orow = out + warp * R_;
    for (int jj = lane; jj < R_; jj += 32) orow[jj] = row[jj] - lse;
}

// ------------------------------ host helpers -------------------------------
static void launch_gemm(const GArgs& a) {
    dim3 grid((a.N + GBN - 1) / GBN, (a.M + GBM - 1) / GBM, 1);
    gemm_nt_kernel<<<grid, 256>>>(a, a);
}
static void launch_gemm2(const GArgs& a, const GArgs& b) {
    int M = a.M > b.M ? a.M : b.M;
    int N = a.N > b.N ? a.N : b.N;
    dim3 grid((N + GBN - 1) / GBN, (M + GBM - 1) / GBM, 2);
    gemm_nt_kernel<<<grid, 256>>>(a, b);
}
template <typename Tp>
static float* sym_addr(Tp& sym) {
    void* p = nullptr;
    cudaGetSymbolAddress(&p, sym);
    return (float*)p;
}

} // anonymous namespace

extern "C" void kernel_launch(void* const* d_in, const int* in_sizes, int n_in,
                              void* d_out, int out_size) {
    (void)in_sizes; (void)n_in; (void)out_size;
    const float* x        = (const float*)d_in[0];
    const float* chroma   = (const float*)d_in[1];
    const float* eps      = (const float*)d_in[2];
    const float* w_ih_f   = (const float*)d_in[3];
    const float* w_hh_f   = (const float*)d_in[4];
    const float* b_ih_f   = (const float*)d_in[5];
    const float* b_hh_f   = (const float*)d_in[6];
    const float* w_ih_b   = (const float*)d_in[7];
    const float* w_hh_b   = (const float*)d_in[8];
    const float* b_ih_b   = (const float*)d_in[9];
    const float* b_hh_b   = (const float*)d_in[10];
    const float* w_mu     = (const float*)d_in[11];
    const float* b_mu     = (const float*)d_in[12];
    const float* w_var    = (const float*)d_in[13];
    const float* b_var    = (const float*)d_in[14];
    const float* w_init   = (const float*)d_in[15];
    const float* b_init   = (const float*)d_in[16];
    const float* w_ih_g   = (const float*)d_in[17];
    const float* w_hh_g   = (const float*)d_in[18];
    const float* b_ih_g   = (const float*)d_in[19];
    const float* b_hh_g   = (const float*)d_in[20];
    const float* w_ih_g2  = (const float*)d_in[21];
    const float* w_hh_g2  = (const float*)d_in[22];
    const float* b_ih_g2  = (const float*)d_in[23];
    const float* b_hh_g2  = (const float*)d_in[24];
    const float* w_out    = (const float*)d_in[25];
    const float* b_out    = (const float*)d_in[26];

    float* out = (float*)d_out;
    const long MU_OFF  = BT_ * R_;
    const long STD_OFF = MU_OFF + (long)B_ * Z2_;
    const long Z_OFF   = STD_OFF + (long)B_ * Z2_;

    float* p_gif   = sym_addr(g_gif);
    float* p_gib   = sym_addr(g_gib);
    float* p_gid   = sym_addr(g_gid);
    float* p_zi    = sym_addr(g_zi);
    float* p_h0    = sym_addr(g_h0);
    float* p_h1all = sym_addr(g_h1all);
    float* p_henc  = sym_addr(g_henc);
    float* p_var   = sym_addr(g_var);
    float* p_zbuf  = sym_addr(g_zbuf);
    float* p_decin = sym_addr(g_decin);
    float* p_logit = sym_addr(g_logits);

    // 1. prologue: zero h, reset barrier, build dec_in
    init_kernel<<<512, 256>>>(x);

    // 2. encoder input gates for all timesteps (both directions)
    GArgs gif{x, R_, w_ih_f, R_, b_ih_f, p_gif, H3_, (int)BT_, H3_, R_};
    GArgs gib{x, R_, w_ih_b, R_, b_ih_b, p_gib, H3_, (int)BT_, H3_, R_};
    launch_gemm2(gif, gib);

    // 3. decoder dec_in input gates (first 130 cols of w_ih_g)
    GArgs gid{p_decin, R_, w_ih_g, 410, nullptr, p_gid, H3_, (int)BT_, H3_, R_};
    launch_gemm(gid);

    // 4. persistent bidirectional encoder recurrence
    encoder_kernel<<<NB, 256>>>(w_hh_f, b_hh_f, w_hh_b, b_hh_b);

    // 5. concat final hiddens
    henc_kernel<<<(B_ * H_ + 255) / 256, 256>>>();

    // 6. VAE head
    GArgs gmu {p_henc, 2 * H_, w_mu,  2 * H_, b_mu,  out + MU_OFF, Z2_, B_, Z2_, 2 * H_};
    GArgs gvar{p_henc, 2 * H_, w_var, 2 * H_, b_var, p_var,        Z2_, B_, Z2_, 2 * H_};
    launch_gemm2(gmu, gvar);

    // 7. reparameterize + concat chroma
    zstd_kernel<<<B_, 288>>>(eps, chroma, out + MU_OFF, out + STD_OFF, out + Z_OFF);

    // 8. hx0 = z @ w_init^T + b_init ; zi = z @ w_ih_g[:,130:]^T + b_ih_g
    GArgs ghx0{p_zbuf, ZC_, w_init, ZC_, b_init, p_h0, H_, B_, H_, ZC_};
    GArgs gzi {p_zbuf, ZC_, w_ih_g + 130, 410, b_ih_g, p_zi, H3_, B_, H3_, ZC_};
    launch_gemm2(ghx0, gzi);

    // 9. persistent 2-layer decoder recurrence
    decoder_kernel<<<NB, 256>>>(w_hh_g, b_hh_g, w_ih_g2, w_hh_g2, b_ih_g2, b_hh_g2);

    // 10. batched output projection
    GArgs glog{p_h1all, H_, w_out, H_, b_out, p_logit, R_, (int)BT_, R_, H_};
    launch_gemm(glog);

    // 11. log_softmax
    logsoftmax_kernel<<<(int)((BT_ * 32 + 255) / 256), 256>>>(p_logit, out);
}

// round 5
// speedup vs baseline: 1.0072x; 1.0072x over previous
#include <cuda_runtime.h>
#include <cstdint>
#include <math.h>

namespace {

typedef unsigned long long ull;

constexpr int  B_  = 128;
constexpr int  T_  = 256;
constexpr int  R_  = 130;
constexpr int  H_  = 1024;
constexpr int  H3_ = 3072;
constexpr int  Z2_ = 256;
constexpr int  C_  = 24;
constexpr int  ZC_ = 280;                 // Z2 + C
constexpr long BT_ = (long)B_ * T_;       // 32768
constexpr long BH_ = (long)B_ * H_;

constexpr int NB = 128;   // persistent grid size (must all be co-resident)
constexpr int KC = 32;    // k-chunk (recurrent kernels)
constexpr int MT = 64;    // m tile (recurrent kernels)
constexpr int NJ = 16;    // j (h-column) tile (recurrent kernels)

// ------------------------- device scratch ----------------------------------
__device__ float g_hf[2][B_ * H_];
__device__ float g_hb[2][B_ * H_];
__device__ float g_h0[2][B_ * H_];
__device__ float g_h1[2][B_ * H_];
__device__ float g_gif[BT_ * H3_];        // encoder fwd input gates, row m=b*T+t
__device__ float g_gib[BT_ * H3_];        // encoder bwd input gates
__device__ float g_gid[BT_ * H3_];        // decoder dec_in input gates
__device__ float g_zi [B_ * H3_];         // z-part of decoder L1 gates (+b_ih_g)
__device__ float g_h1all[BT_ * H_];       // all decoder layer-2 hiddens
__device__ float g_henc[B_ * 2 * H_];
__device__ float g_var [B_ * Z2_];
__device__ float g_zbuf[B_ * ZC_];
__device__ float g_decin[BT_ * R_];
__device__ float g_logits[BT_ * R_];
__device__ unsigned g_bar_count;
__device__ volatile unsigned g_bar_gen;

// --------------------------- f32x2 helpers ---------------------------------
__device__ __forceinline__ ull pack2(float x, float y) {
    ull r; asm("mov.b64 %0, {%1, %2};" : "=l"(r) : "f"(x), "f"(y)); return r;
}
__device__ __forceinline__ float2 unpack2(ull v) {
    float2 f; asm("mov.b64 {%0, %1}, %2;" : "=f"(f.x), "=f"(f.y) : "l"(v)); return f;
}
__device__ __forceinline__ void fma2(ull& d, ull a, ull b) {
    asm("fma.rn.f32x2 %0, %1, %2, %0;" : "+l"(d) : "l"(a), "l"(b));
}
__device__ __forceinline__ float sigmoidf_(float x) { return 1.f / (1.f + expf(-x)); }

// ------------------------ software grid barrier ----------------------------
__device__ __forceinline__ void grid_barrier() {
    __syncthreads();
    if (threadIdx.x == 0) {
        unsigned gen = g_bar_gen;
        __threadfence();
        if (atomicAdd(&g_bar_count, 1u) == (unsigned)(NB - 1)) {
            g_bar_count = 0;
            __threadfence();
            g_bar_gen = gen + 1;
        } else {
            while (g_bar_gen == gen) { }
        }
        __threadfence();
    }
    __syncthreads();
}

// ------------------------------- GEMM --------------------------------------
// C[M,N] = A[M,K] (row-major) @ W[N,K]^T (row-major) + bias  (f32x2 packed)
struct GArgs {
    const float* A;  long lda;
    const float* W;  long ldw;
    const float* bias;
    float*       C;  long ldc;
    int M, N, K;
};

constexpr int GBM = 128, GBN = 128, GBK = 16;

// 256 threads; each thread computes 8 rows x 8 cols.
// Rows packed in f32x2 pairs (4 pairs); B duplicated as f32x2 in smem.
// B smem layout: Bs[kk][(n&7)*16 + (n>>3)] so inner-loop loads (c*16+tx) are
// conflict-free (consecutive ull across lanes).
__global__ void __launch_bounds__(256, 2) gemm_nt_kernel(GArgs g0, GArgs g1) {
    GArgs g = (blockIdx.z == 0) ? g0 : g1;
    const int bm = blockIdx.y * GBM;
    const int bn = blockIdx.x * GBN;
    if (bm >= g.M || bn >= g.N) return;

    __shared__ float As[GBK][GBM + 4];
    __shared__ ull   Bs[GBK][GBN + 1];

    const int tid = threadIdx.x;
    const int tx  = tid & 15;       // 16 col groups of 8
    const int ty  = tid >> 4;       // 16 row groups of 8
    const int r0  = ty * 8;

    ull acc[4][8];
#pragma unroll
    for (int p = 0; p < 4; p++)
#pragma unroll
        for (int c = 0; c < 8; c++) acc[p][c] = 0ull;

    for (int k0 = 0; k0 < g.K; k0 += GBK) {
        // load A: 128x16, 8 per thread
#pragma unroll
        for (int i = 0; i < 8; i++) {
            int idx = tid + i * 256;
            int m = idx >> 4, kk = idx & 15;
            int gm = bm + m, gk = k0 + kk;
            float v = 0.f;
            if (gm < g.M && gk < g.K) v = g.A[(long)gm * g.lda + gk];
            As[kk][m] = v;
        }
        // load B (duplicated to f32x2): 128x16, 8 per thread
#pragma unroll
        for (int i = 0; i < 8; i++) {
            int idx = tid + i * 256;
            int n = idx >> 4, kk = idx & 15;
            int gn = bn + n, gk = k0 + kk;
            float v = 0.f;
            if (gn < g.N && gk < g.K) v = g.W[(long)gn * g.ldw + gk];
            Bs[kk][(n & 7) * 16 + (n >> 3)] = pack2(v, v);
        }
        __syncthreads();
#pragma unroll
        for (int kk = 0; kk < GBK; kk++) {
            ull a[4], b[8];
#pragma unroll
            for (int p = 0; p < 4; p++) a[p] = *(const ull*)&As[kk][r0 + 2 * p];
#pragma unroll
            for (int c = 0; c < 8; c++) b[c] = Bs[kk][c * 16 + tx];
#pragma unroll
            for (int p = 0; p < 4; p++)
#pragma unroll
                for (int c = 0; c < 8; c++) fma2(acc[p][c], a[p], b[c]);
        }
        __syncthreads();
    }

#pragma unroll
    for (int p = 0; p < 4; p++) {
        int gm = bm + r0 + 2 * p;
#pragma unroll
        for (int c = 0; c < 8; c++) {
            int gn = bn + tx * 8 + c;
            if (gn >= g.N) continue;
            float2 v = unpack2(acc[p][c]);
            float bias = g.bias ? g.bias[gn] : 0.f;
            if (gm < g.M)     g.C[(long)gm * g.ldc + gn]       = v.x + bias;
            if (gm + 1 < g.M) g.C[(long)(gm + 1) * g.ldc + gn] = v.y + bias;
        }
    }
}

// -------------------- persistent encoder (bidirectional GRU) ---------------
__global__ void __launch_bounds__(256, 1)
encoder_kernel(const float* __restrict__ w_f, const float* __restrict__ bh_f,
               const float* __restrict__ w_b, const float* __restrict__ bh_b) {
    __shared__ float As[KC][MT + 2];                 // 8448 B
    __shared__ ull   Bs[3][KC][NJ + 1];              // 13056 B
    const int tid = threadIdx.x;
    const int tx  = tid & 15;       // h-column within tile
    const int ty  = tid >> 4;       // row group
    const int r0  = ty * 4;

#pragma unroll 1
    for (int t = 0; t < T_; t++) {
        const float* hfc = g_hf[t & 1];       float* hfn = g_hf[(t + 1) & 1];
        const float* hbc = g_hb[t & 1];       float* hbn = g_hb[(t + 1) & 1];
#pragma unroll 1
        for (int job = blockIdx.x; job < 256; job += NB) {
            const int jt  = job >> 2;
            const int dir = (job >> 1) & 1;
            const int mt  = job & 1;
            const float* h       = dir ? hbc : hfc;
            float*       hn_out  = dir ? hbn : hfn;
            const float* W       = dir ? w_b : w_f;
            const float* bh      = dir ? bh_b : bh_f;
            const float* gi_base = dir ? g_gib : g_gif;
            const int tstep = dir ? (T_ - 1 - t) : t;
            const int m0 = mt * MT;
            const int j0 = jt * NJ;

            ull ar[2] = {0ull, 0ull}, az[2] = {0ull, 0ull}, an[2] = {0ull, 0ull};
#pragma unroll 1
            for (int k0 = 0; k0 < H_; k0 += KC) {
                __syncthreads();
#pragma unroll
                for (int i = 0; i < 8; i++) {           // 64x32 A tile
                    int f = tid + i * 256;
                    int m = f >> 5, kk = f & 31;
                    As[kk][m] = h[(long)(m0 + m) * H_ + k0 + kk];
                }
#pragma unroll
                for (int i = 0; i < 6; i++) {           // 3x16x32 gate weights
                    int f = tid + i * 256;
                    int gg = f >> 9;
                    int r  = f & 511;
                    int n = r >> 5, kk = r & 31;
                    float w = W[(long)(gg * H_ + j0 + n) * H_ + k0 + kk];
                    Bs[gg][kk][n] = pack2(w, w);
                }
                __syncthreads();
#pragma unroll
                for (int kk = 0; kk < KC; kk++) {
                    ull a0 = *(const ull*)&As[kk][r0];
                    ull a1 = *(const ull*)&As[kk][r0 + 2];
                    ull br = Bs[0][kk][tx];
                    ull bz = Bs[1][kk][tx];
                    ull bn = Bs[2][kk][tx];
                    fma2(ar[0], a0, br); fma2(ar[1], a1, br);
                    fma2(az[0], a0, bz); fma2(az[1], a1, bz);
                    fma2(an[0], a0, bn); fma2(an[1], a1, bn);
                }
            }
            // fused GRU epilogue
            const int j = j0 + tx;
            const float bhr = bh[j], bhz = bh[H_ + j], bhn = bh[2 * H_ + j];
#pragma unroll
            for (int p = 0; p < 2; p++) {
                float2 hr2 = unpack2(ar[p]);
                float2 hz2 = unpack2(az[p]);
                float2 hn2 = unpack2(an[p]);
#pragma unroll
                for (int q = 0; q < 2; q++) {
                    int m = m0 + r0 + p * 2 + q;
                    float hr = (q ? hr2.y : hr2.x) + bhr;
                    float hz = (q ? hz2.y : hz2.x) + bhz;
                    float hn = (q ? hn2.y : hn2.x) + bhn;
                    long gio = ((long)m * T_ + tstep) * H3_ + j;
                    float ir  = gi_base[gio];
                    float iz  = gi_base[gio + H_];
                    float inn = gi_base[gio + 2 * H_];
                    float rr = sigmoidf_(ir + hr);
                    float u  = sigmoidf_(iz + hz);
                    float nn = tanhf(inn + rr * hn);
                    float hp = h[(long)m * H_ + j];
                    hn_out[(long)m * H_ + j] = (1.f - u) * nn + u * hp;
                }
            }
        }
        grid_barrier();
    }
}

// -------------------- persistent decoder (2-layer GRU) ---------------------
__global__ void __launch_bounds__(256, 1)
decoder_kernel(const float* __restrict__ w_hh_g,  const float* __restrict__ b_hh_g,
               const float* __restrict__ w_ih_g2, const float* __restrict__ w_hh_g2,
               const float* __restrict__ b_ih_g2, const float* __restrict__ b_hh_g2) {
    __shared__ __align__(16) char smem[43008];
    float* AsF  = (float*)smem;                 // [KC][66]   (A tile 1)
    float* As2F = (float*)(smem + 8448);        // [KC][66]   (A tile 2, phase B)
    ull*   BsA  = (ull*)(smem + 8448);          // phase A: 3*KC*17
    ull*   BsB  = (ull*)(smem + 16896);         // phase B: 6*KC*17

    const int tid = threadIdx.x;
    const int tx  = tid & 15;
    const int ty  = tid >> 4;
    const int r0  = ty * 4;
    const int job = blockIdx.x;                  // 128 jobs, 1 per block
    const int mt  = job & 1, jt = job >> 1;
    const int m0  = mt * MT, j0 = jt * NJ;
    const int j   = j0 + tx;

#pragma unroll 1
    for (int t = 0; t < T_; t++) {
        const float* h0c = g_h0[t & 1];
        float*       h0n = g_h0[(t + 1) & 1];
        // ---------------- phase A: layer-1 GRU ----------------
        {
            ull ar[2] = {0ull, 0ull}, az[2] = {0ull, 0ull}, an[2] = {0ull, 0ull};
#pragma unroll 1
            for (int k0 = 0; k0 < H_; k0 += KC) {
                __syncthreads();
#pragma unroll
                for (int i = 0; i < 8; i++) {
                    int f = tid + i * 256;
                    int m = f >> 5, kk = f & 31;
                    AsF[kk * 66 + m] = h0c[(long)(m0 + m) * H_ + k0 + kk];
                }
#pragma unroll
                for (int i = 0; i < 6; i++) {
                    int f = tid + i * 256;
                    int gg = f >> 9;
                    int r  = f & 511;
                    int n = r >> 5, kk = r & 31;
                    float w = w_hh_g[(long)(gg * H_ + j0 + n) * H_ + k0 + kk];
                    BsA[(gg * KC + kk) * 17 + n] = pack2(w, w);
                }
                __syncthreads();
#pragma unroll
                for (int kk = 0; kk < KC; kk++) {
                    ull a0 = *(const ull*)&AsF[kk * 66 + r0];
                    ull a1 = *(const ull*)&AsF[kk * 66 + r0 + 2];
                    ull br = BsA[(0 * KC + kk) * 17 + tx];
                    ull bz = BsA[(1 * KC + kk) * 17 + tx];
                    ull bn = BsA[(2 * KC + kk) * 17 + tx];
                    fma2(ar[0], a0, br); fma2(ar[1], a1, br);
                    fma2(az[0], a0, bz); fma2(az[1], a1, bz);
                    fma2(an[0], a0, bn); fma2(an[1], a1, bn);
                }
            }
            const float bhr = b_hh_g[j], bhz = b_hh_g[H_ + j], bhn = b_hh_g[2 * H_ + j];
#pragma unroll
            for (int p = 0; p < 2; p++) {
                float2 hr2 = unpack2(ar[p]);
                float2 hz2 = unpack2(az[p]);
                float2 hn2 = unpack2(an[p]);
#pragma unroll
                for (int q = 0; q < 2; q++) {
                    int m = m0 + r0 + p * 2 + q;
                    float hr = (q ? hr2.y : hr2.x) + bhr;
                    float hz = (q ? hz2.y : hz2.x) + bhz;
                    float hn = (q ? hn2.y : hn2.x) + bhn;
                    long zo = (long)m * H3_ + j;
                    long dof = ((long)m * T_ + t) * H3_ + j;
                    float ir  = g_gid[dof]           + g_zi[zo];
                    float iz  = g_gid[dof + H_]      + g_zi[zo + H_];
                    float inn = g_gid[dof + 2 * H_]  + g_zi[zo + 2 * H_];
                    float rr = sigmoidf_(ir + hr);
                    float u  = sigmoidf_(iz + hz);
                    float nn = tanhf(inn + rr * hn);
                    float hp = h0c[(long)m * H_ + j];
                    h0n[(long)m * H_ + j] = (1.f - u) * nn + u * hp;
                }
            }
        }
        grid_barrier();
        // ---------------- phase B: layer-2 GRU ----------------
        {
            const float* h1p = (t == 0) ? h0n : g_h1[t & 1];
            float*       h1n = g_h1[(t + 1) & 1];
            ull air[2] = {0ull, 0ull}, aiz[2] = {0ull, 0ull}, ain[2] = {0ull, 0ull};
            ull ahr[2] = {0ull, 0ull}, ahz[2] = {0ull, 0ull}, ahn[2] = {0ull, 0ull};
#pragma unroll 1
            for (int k0 = 0; k0 < H_; k0 += KC) {
                __syncthreads();
#pragma unroll
                for (int i = 0; i < 8; i++) {
                    int f = tid + i * 256;
                    int m = f >> 5, kk = f & 31;
                    AsF [kk * 66 + m] = h0n[(long)(m0 + m) * H_ + k0 + kk];
                    As2F[kk * 66 + m] = h1p[(long)(m0 + m) * H_ + k0 + kk];
                }
#pragma unroll
                for (int i = 0; i < 12; i++) {
                    int f = tid + i * 256;
                    int gg = f >> 9;
                    int r  = f & 511;
                    int n = r >> 5, kk = r & 31;
                    const float* W = (gg < 3) ? w_ih_g2 : w_hh_g2;
                    int gs = (gg < 3) ? gg : gg - 3;
                    float w = W[(long)(gs * H_ + j0 + n) * H_ + k0 + kk];
                    BsB[(gg * KC + kk) * 17 + n] = pack2(w, w);
                }
                __syncthreads();
#pragma unroll
                for (int kk = 0; kk < KC; kk++) {
                    ull a0 = *(const ull*)&AsF [kk * 66 + r0];
                    ull a1 = *(const ull*)&AsF [kk * 66 + r0 + 2];
                    ull c0 = *(const ull*)&As2F[kk * 66 + r0];
                    ull c1 = *(const ull*)&As2F[kk * 66 + r0 + 2];
                    ull bir = BsB[(0 * KC + kk) * 17 + tx];
                    ull biz = BsB[(1 * KC + kk) * 17 + tx];
                    ull bin = BsB[(2 * KC + kk) * 17 + tx];
                    ull bhr = BsB[(3 * KC + kk) * 17 + tx];
                    ull bhz = BsB[(4 * KC + kk) * 17 + tx];
                    ull bhn = BsB[(5 * KC + kk) * 17 + tx];
                    fma2(air[0], a0, bir); fma2(air[1], a1, bir);
                    fma2(aiz[0], a0, biz); fma2(aiz[1], a1, biz);
                    fma2(ain[0], a0, bin); fma2(ain[1], a1, bin);
                    fma2(ahr[0], c0, bhr); fma2(ahr[1], c1, bhr);
                    fma2(ahz[0], c0, bhz); fma2(ahz[1], c1, bhz);
                    fma2(ahn[0], c0, bhn); fma2(ahn[1], c1, bhn);
                }
            }
            const float bir = b_ih_g2[j], biz = b_ih_g2[H_ + j], bin2 = b_ih_g2[2 * H_ + j];
            const float bhr = b_hh_g2[j], bhz = b_hh_g2[H_ + j], bhn2 = b_hh_g2[2 * H_ + j];
#pragma unroll
            for (int p = 0; p < 2; p++) {
                float2 ir2 = unpack2(air[p]), iz2 = unpack2(aiz[p]), in2 = unpack2(ain[p]);
                float2 hr2 = unpack2(ahr[p]), hz2 = unpack2(ahz[p]), hn2 = unpack2(ahn[p]);
#pragma unroll
                for (int q = 0; q < 2; q++) {
                    int m = m0 + r0 + p * 2 + q;
                    float rr = sigmoidf_(((q ? ir2.y : ir2.x) + bir) + ((q ? hr2.y : hr2.x) + bhr));
                    float u  = sigmoidf_(((q ? iz2.y : iz2.x) + biz) + ((q ? hz2.y : hz2.x) + bhz));
                    float nn = tanhf(((q ? in2.y : in2.x) + bin2) + rr * ((q ? hn2.y : hn2.x) + bhn2));
                    float hp = h1p[(long)m * H_ + j];
                    float v = (1.f - u) * nn + u * hp;
                    h1n[(long)m * H_ + j] = v;
                    g_h1all[((long)m * T_ + t) * H_ + j] = v;
                }
            }
        }
        grid_barrier();
    }
}

// --------------------------- elementwise kernels ---------------------------
__global__ void init_kernel(const float* __restrict__ x) {
    long stride = (long)gridDim.x * blockDim.x;
    long i0 = (long)blockIdx.x * blockDim.x + threadIdx.x;
    if (i0 == 0) { g_bar_count = 0; g_bar_gen = 0; }
    for (long i = i0; i < BH_; i += stride) { g_hf[0][i] = 0.f; g_hb[0][i] = 0.f; }
    for (long i = i0; i < BT_ * R_; i += stride) {
        int  r = (int)(i % R_);
        long m = i / R_;
        int  t = (int)(m % T_);
        g_decin[i] = (t == 0) ? ((r == R_ - 1) ? 1.f : 0.f) : x[i - R_];
    }
}

__global__ void henc_kernel() {
    int i = blockIdx.x * blockDim.x + threadIdx.x;
    if (i >= B_ * H_) return;
    int b = i / H_, jj = i % H_;
    g_henc[(long)b * 2 * H_ + jj]      = g_hf[0][i];
    g_henc[(long)b * 2 * H_ + H_ + jj] = g_hb[0][i];
}

__global__ void zstd_kernel(const float* __restrict__ eps,
                            const float* __restrict__ chroma,
                            const float* __restrict__ mu_out,
                            float* __restrict__ std_out,
                            float* __restrict__ z_out) {
    int b = blockIdx.x;
    int jj = threadIdx.x;
    if (jj < Z2_) {
        float mu = mu_out[(long)b * Z2_ + jj];
        float sd = expf(g_var[(long)b * Z2_ + jj]);
        float z  = mu + sd * eps[(long)b * Z2_ + jj];
        std_out[(long)b * Z2_ + jj] = sd;
        z_out[(long)b * ZC_ + jj]   = z;
        g_zbuf[(long)b * ZC_ + jj]  = z;
    } else if (jj < ZC_) {
        float cv = chroma[(long)b * C_ + (jj - Z2_)];
        z_out[(long)b * ZC_ + jj]  = cv;
        g_zbuf[(long)b * ZC_ + jj] = cv;
    }
}

__global__ void logsoftmax_kernel(const float* __restrict__ logits,
                                  float* __restrict__ out) {
    long warp = ((long)blockIdx.x * blockDim.x + threadIdx.x) >> 5;
    int  lane = threadIdx.x & 31;
    if (warp >= BT_) return;
    const float* row = logits + warp * R_;
    float mx = -1e30f;
    for (int jj = lane; jj < R_; jj += 32) mx = fmaxf(mx, row[jj]);
#pragma unroll
    for (int o = 16; o; o >>= 1) mx = fmaxf(mx, __shfl_xor_sync(0xffffffff, mx, o));
    float s = 0.f;
    for (int jj = lane; jj < R_; jj += 32) s += expf(row[jj] - mx);
#pragma unroll
    for (int o = 16; o; o >>= 1) s += __shfl_xor_sync(0xffffffff, s, o);
    float lse = mx + logf(s);
    float* orow = out + warp * R_;
    for (int jj = lane; jj < R_; jj += 32) orow[jj] = row[jj] - lse;
}

// ------------------------------ host helpers -------------------------------
static void launch_gemm(const GArgs& a) {
    dim3 grid((a.N + GBN - 1) / GBN, (a.M + GBM - 1) / GBM, 1);
    gemm_nt_kernel<<<grid, 256>>>(a, a);
}
static void launch_gemm2(const GArgs& a, const GArgs& b) {
    int M = a.M > b.M ? a.M : b.M;
    int N = a.N > b.N ? a.N : b.N;
    dim3 grid((N + GBN - 1) / GBN, (M + GBM - 1) / GBM, 2);
    gemm_nt_kernel<<<grid, 256>>>(a, b);
}
template <typename Tp>
static float* sym_addr(Tp& sym) {
    void* p = nullptr;
    cudaGetSymbolAddress(&p, sym);
    return (float*)p;
}

} // anonymous namespace

extern "C" void kernel_launch(void* const* d_in, const int* in_sizes, int n_in,
                              void* d_out, int out_size) {
    (void)in_sizes; (void)n_in; (void)out_size;
    const float* x        = (const float*)d_in[0];
    const float* chroma   = (const float*)d_in[1];
    const float* eps      = (const float*)d_in[2];
    const float* w_ih_f   = (const float*)d_in[3];
    const float* w_hh_f   = (const float*)d_in[4];
    const float* b_ih_f   = (const float*)d_in[5];
    const float* b_hh_f   = (const float*)d_in[6];
    const float* w_ih_b   = (const float*)d_in[7];
    const float* w_hh_b   = (const float*)d_in[8];
    const float* b_ih_b   = (const float*)d_in[9];
    const float* b_hh_b   = (const float*)d_in[10];
    const float* w_mu     = (const float*)d_in[11];
    const float* b_mu     = (const float*)d_in[12];
    const float* w_var    = (const float*)d_in[13];
    const float* b_var    = (const float*)d_in[14];
    const float* w_init   = (const float*)d_in[15];
    const float* b_init   = (const float*)d_in[16];
    const float* w_ih_g   = (const float*)d_in[17];
    const float* w_hh_g   = (const float*)d_in[18];
    const float* b_ih_g   = (const float*)d_in[19];
    const float* b_hh_g   = (const float*)d_in[20];
    const float* w_ih_g2  = (const float*)d_in[21];
    const float* w_hh_g2  = (const float*)d_in[22];
    const float* b_ih_g2  = (const float*)d_in[23];
    const float* b_hh_g2  = (const float*)d_in[24];
    const float* w_out    = (const float*)d_in[25];
    const float* b_out    = (const float*)d_in[26];

    float* out = (float*)d_out;
    const long MU_OFF  = BT_ * R_;
    const long STD_OFF = MU_OFF + (long)B_ * Z2_;
    const long Z_OFF   = STD_OFF + (long)B_ * Z2_;

    float* p_gif   = sym_addr(g_gif);
    float* p_gib   = sym_addr(g_gib);
    float* p_gid   = sym_addr(g_gid);
    float* p_zi    = sym_addr(g_zi);
    float* p_h0    = sym_addr(g_h0);
    float* p_h1all = sym_addr(g_h1all);
    float* p_henc  = sym_addr(g_henc);
    float* p_var   = sym_addr(g_var);
    float* p_zbuf  = sym_addr(g_zbuf);
    float* p_decin = sym_addr(g_decin);
    float* p_logit = sym_addr(g_logits);

    // 1. prologue: zero h, reset barrier, build dec_in
    init_kernel<<<512, 256>>>(x);

    // 2. encoder input gates for all timesteps (both directions)
    GArgs gif{x, R_, w_ih_f, R_, b_ih_f, p_gif, H3_, (int)BT_, H3_, R_};
    GArgs gib{x, R_, w_ih_b, R_, b_ih_b, p_gib, H3_, (int)BT_, H3_, R_};
    launch_gemm2(gif, gib);

    // 3. decoder dec_in input gates (first 130 cols of w_ih_g)
    GArgs gid{p_decin, R_, w_ih_g, 410, nullptr, p_gid, H3_, (int)BT_, H3_, R_};
    launch_gemm(gid);

    // 4. persistent bidirectional encoder recurrence
    encoder_kernel<<<NB, 256>>>(w_hh_f, b_hh_f, w_hh_b, b_hh_b);

    // 5. concat final hiddens
    henc_kernel<<<(B_ * H_ + 255) / 256, 256>>>();

    // 6. VAE head
    GArgs gmu {p_henc, 2 * H_, w_mu,  2 * H_, b_mu,  out + MU_OFF, Z2_, B_, Z2_, 2 * H_};
    GArgs gvar{p_henc, 2 * H_, w_var, 2 * H_, b_var, p_var,        Z2_, B_, Z2_, 2 * H_};
    launch_gemm2(gmu, gvar);

    // 7. reparameterize + concat chroma
    zstd_kernel<<<B_, 288>>>(eps, chroma, out + MU_OFF, out + STD_OFF, out + Z_OFF);

    // 8. hx0 = z @ w_init^T + b_init ; zi = z @ w_ih_g[:,130:]^T + b_ih_g
    GArgs ghx0{p_zbuf, ZC_, w_init, ZC_, b_init, p_h0, H_, B_, H_, ZC_};
    GArgs gzi {p_zbuf, ZC_, w_ih_g + 130, 410, b_ih_g, p_zi, H3_, B_, H3_, ZC_};
    launch_gemm2(ghx0, gzi);

    // 9. persistent 2-layer decoder recurrence
    decoder_kernel<<<NB, 256>>>(w_hh_g, b_hh_g, w_ih_g2, w_hh_g2, b_ih_g2, b_hh_g2);

    // 10. batched output projection
    GArgs glog{p_h1all, H_, w_out, H_, b_out, p_logit, R_, (int)BT_, R_, H_};
    launch_gemm(glog);

    // 11. log_softmax
    logsoftmax_kernel<<<(int)((BT_ * 32 + 255) / 256), 256>>>(p_logit, out);
}